// round 16
// baseline (speedup 1.0000x reference)
#include <cuda_runtime.h>
#include <cuda_fp16.h>
#include <math.h>
#include <stdint.h>

#define BN 4096
#define DN 64
#define HN 512

// ---------------- scratch (__device__ globals; no allocation) ----------------
__device__ __half g_h1h[BN*HN];
__device__ __half g_h1l[BN*HN];
__device__ __half g_g1h[BN*HN];
__device__ __half g_g1l[BN*HN];
__device__ __half g_d1h[BN*HN];
__device__ __half g_d2h[BN*HN];
__device__ float  g_h2[BN*HN];
__device__ float  g_g2[BN*HN];
__device__ float  g_q [BN*DN];
__device__ float  g_w1t[DN*HN];     /* W1 transposed: [d][k], coalesced per-CTA read */
__device__ __half g_w2h[HN*HN];
__device__ __half g_w2l[HN*HN];
__device__ __half g_v2h[HN*HN];
__device__ __half g_v2l[HN*HN];

__device__ __forceinline__ uint32_t smem_u32(const void* p) {
    return (uint32_t)__cvta_generic_to_shared(p);
}

__device__ __forceinline__ void ldsm4(uint32_t* r, uint32_t addr) {
    asm volatile("ldmatrix.sync.aligned.m8n8.x4.shared.b16 {%0,%1,%2,%3}, [%4];"
        : "=r"(r[0]), "=r"(r[1]), "=r"(r[2]), "=r"(r[3]) : "r"(addr));
}

__device__ __forceinline__ void mma_f16(float* c, const uint32_t* a, const uint32_t* b) {
    asm volatile(
        "mma.sync.aligned.m16n8k16.row.col.f32.f16.f16.f32 "
        "{%0,%1,%2,%3}, {%4,%5,%6,%7}, {%8,%9}, {%0,%1,%2,%3};"
        : "+f"(c[0]), "+f"(c[1]), "+f"(c[2]), "+f"(c[3])
        : "r"(a[0]), "r"(a[1]), "r"(a[2]), "r"(a[3]), "r"(b[0]), "r"(b[1]));
}

// ---------------------------------------------------------------------------
// K0: W2, V2 -> fp16 hi/lo ;  K0b: W1 -> transposed fp32
// ---------------------------------------------------------------------------
__global__ void k0_kernel(const float* __restrict__ W2, const float* __restrict__ V2) {
    int i = blockIdx.x * 512 + threadIdx.x;
    float w = W2[i];
    __half wh = __float2half_rn(w);
    g_w2h[i] = wh;
    g_w2l[i] = __float2half_rn(w - __half2float(wh));
    float v = V2[i];
    __half vh = __float2half_rn(v);
    g_v2h[i] = vh;
    g_v2l[i] = __float2half_rn(v - __half2float(vh));
}

__global__ void k0b_kernel(const float* __restrict__ W1) {
    // one block per d; threads stride over k (read coalesced over d within W1 rows)
    const int d = blockIdx.x;
    for (int k = threadIdx.x; k < HN; k += 512)
        g_w1t[d * HN + k] = W1[k * DN + d];
}

// ---------------------------------------------------------------------------
// K1: h1 = tanh(mu@W1^T + b1) -> fp16 hi/lo + d1h; g1 = tanh(mu@V1^T+c1) -> hi/lo
// ---------------------------------------------------------------------------
__global__ __launch_bounds__(512) void k1_kernel(
    const float* __restrict__ states,
    const float* __restrict__ W1, const float* __restrict__ b1,
    const float* __restrict__ V1, const float* __restrict__ c1)
{
    __shared__ float mu_s[8][64];
    const int b0 = blockIdx.x * 8;
    const int t = threadIdx.x;
    {
        int bb = t >> 6, dd = t & 63;
        mu_s[bb][dd] = states[(b0 + bb) * (2*DN) + dd];
    }
    __syncthreads();
    const int h = t;
    float acc1[8], acc2[8];
    #pragma unroll
    for (int i = 0; i < 8; i++) { acc1[i] = 0.f; acc2[i] = 0.f; }
    const float4* w1r = (const float4*)(W1 + h * DN);
    const float4* v1r = (const float4*)(V1 + h * DN);
    #pragma unroll
    for (int q = 0; q < DN/4; q++) {
        float4 w = w1r[q];
        float4 v = v1r[q];
        #pragma unroll
        for (int bb = 0; bb < 8; bb++) {
            float4 m = *(const float4*)&mu_s[bb][q*4];
            acc1[bb] += w.x*m.x + w.y*m.y + w.z*m.z + w.w*m.w;
            acc2[bb] += v.x*m.x + v.y*m.y + v.z*m.z + v.w*m.w;
        }
    }
    const float bw = b1[h], bv = c1[h];
    #pragma unroll
    for (int bb = 0; bb < 8; bb++) {
        int idx = (b0 + bb) * HN + h;
        float th = tanhf(acc1[bb] + bw);
        __half hh = __float2half_rn(th);
        g_h1h[idx] = hh;
        g_h1l[idx] = __float2half_rn(th - __half2float(hh));
        g_d1h[idx] = __float2half_rn(1.f - th*th);
        float tg = tanhf(acc2[bb] + bv);
        __half gh = __float2half_rn(tg);
        g_g1h[idx] = gh;
        g_g1l[idx] = __float2half_rn(tg - __half2float(gh));
    }
}

// ---------------------------------------------------------------------------
// K2 (split-fp16 tensor GEMM), verified round 11
// ---------------------------------------------------------------------------
#define A_STRIDE 520
#define B_STRIDE 72
#define B_BUF    (128*B_STRIDE*2)
#define C2_BIAS  0
#define C2_AH    4096
#define C2_AL    (C2_AH + 64*A_STRIDE*2)        /* 70656  */
#define C2_B     (C2_AL + 64*A_STRIDE*2)        /* 137216 */
#define C2_TOT   (C2_B + 4*B_BUF)               /* 210944 */

__global__ __launch_bounds__(256) void k2_kernel(
    const float* __restrict__ b2, const float* __restrict__ c2)
{
    extern __shared__ char smem[];
    const uint32_t sb = smem_u32(smem);
    float* biasS = (float*)(smem + C2_BIAS);

    const int t   = threadIdx.x;
    const int lid = t & 31;
    const int wid = t >> 5;
    const int warp_m = wid >> 2;
    const int warp_n = wid & 3;
    const int z  = blockIdx.y;
    const int b0 = blockIdx.x * 64;

    const __half* in_h = z ? g_g1h : g_h1h;
    const __half* in_l = z ? g_g1l : g_h1l;
    const __half* Bh   = z ? g_v2h : g_w2h;
    const __half* Bl   = z ? g_v2l : g_w2l;
    const float*  bias = z ? c2 : b2;

    for (int i = t; i < HN; i += 256) biasS[i] = bias[i];

    {
        const int row = t >> 2;
        const int kb  = (t & 3) * 128;
        const uint4* sh = (const uint4*)&in_h[(size_t)(b0 + row) * HN + kb];
        const uint4* sl = (const uint4*)&in_l[(size_t)(b0 + row) * HN + kb];
        uint4* dh = (uint4*)((__half*)(smem + C2_AH) + row * A_STRIDE + kb);
        uint4* dl = (uint4*)((__half*)(smem + C2_AL) + row * A_STRIDE + kb);
        #pragma unroll
        for (int j = 0; j < 16; j++) { dh[j] = sh[j]; dl[j] = sl[j]; }
    }

    const int lgrp = lid >> 3;
    const int lr   = lid & 7;
    const uint32_t a_row  = warp_m * 32 + (lgrp & 1) * 8 + lr;
    const uint32_t a_koff = (lgrp >> 1) * 8;
    const uint32_t b_nrow = warp_n * 32 + (lgrp >> 1) * 8 + lr;
    const uint32_t b_koff = (lgrp & 1) * 8;

    float acc[2][4][4];
    #pragma unroll
    for (int mt = 0; mt < 2; mt++)
        #pragma unroll
        for (int nt = 0; nt < 4; nt++)
            #pragma unroll
            for (int j = 0; j < 4; j++) acc[mt][nt][j] = 0.f;

    const int pb_row = t >> 1;
    const int pb_col = (t & 1) * 32;
    uint4 preh[4], prel[4];
    {
        const uint4* sh = (const uint4*)&Bh[(size_t)pb_row * HN + pb_col];
        const uint4* sl = (const uint4*)&Bl[(size_t)pb_row * HN + pb_col];
        #pragma unroll
        for (int j = 0; j < 4; j++) { preh[j] = sh[j]; prel[j] = sl[j]; }
    }
    {
        uint4* dh = (uint4*)((__half*)(smem + C2_B) + pb_row * B_STRIDE + pb_col);
        uint4* dl = (uint4*)((__half*)(smem + C2_B + 2*B_BUF) + pb_row * B_STRIDE + pb_col);
        #pragma unroll
        for (int j = 0; j < 4; j++) { dh[j] = preh[j]; dl[j] = prel[j]; }
    }
    __syncthreads();

    for (int s = 0; s < 32; s++) {
        if (s < 31) {
            const int sn = s + 1;
            const size_t off = (size_t)((sn >> 3) * 128 + pb_row) * HN + (sn & 7) * 64 + pb_col;
            const uint4* sh = (const uint4*)&Bh[off];
            const uint4* sl = (const uint4*)&Bl[off];
            #pragma unroll
            for (int j = 0; j < 4; j++) { preh[j] = sh[j]; prel[j] = sl[j]; }
        }

        const uint32_t bh_base = sb + C2_B + (uint32_t)(s & 1) * B_BUF;
        const uint32_t bl_base = bh_base + 2*B_BUF;
        const int kt = s & 7;
        #pragma unroll
        for (int ks = 0; ks < 4; ks++) {
            const int kabs = kt * 64 + ks * 16;
            uint32_t afh[2][4], afl[2][4], bfh[4][2], bfl[4][2];
            #pragma unroll
            for (int mt = 0; mt < 2; mt++) {
                ldsm4(afh[mt], sb + C2_AH + ((a_row + mt*16) * A_STRIDE + kabs + a_koff) * 2);
                ldsm4(afl[mt], sb + C2_AL + ((a_row + mt*16) * A_STRIDE + kabs + a_koff) * 2);
            }
            #pragma unroll
            for (int pr = 0; pr < 2; pr++) {
                uint32_t r[4];
                ldsm4(r, bh_base + ((b_nrow + pr*16) * B_STRIDE + ks*16 + b_koff) * 2);
                bfh[2*pr][0] = r[0]; bfh[2*pr][1] = r[1];
                bfh[2*pr+1][0] = r[2]; bfh[2*pr+1][1] = r[3];
                ldsm4(r, bl_base + ((b_nrow + pr*16) * B_STRIDE + ks*16 + b_koff) * 2);
                bfl[2*pr][0] = r[0]; bfl[2*pr][1] = r[1];
                bfl[2*pr+1][0] = r[2]; bfl[2*pr+1][1] = r[3];
            }
            #pragma unroll
            for (int mt = 0; mt < 2; mt++)
                #pragma unroll
                for (int nt = 0; nt < 4; nt++)
                    mma_f16(acc[mt][nt], afh[mt], bfh[nt]);
            #pragma unroll
            for (int mt = 0; mt < 2; mt++)
                #pragma unroll
                for (int nt = 0; nt < 4; nt++)
                    mma_f16(acc[mt][nt], afh[mt], bfl[nt]);
            #pragma unroll
            for (int mt = 0; mt < 2; mt++)
                #pragma unroll
                for (int nt = 0; nt < 4; nt++)
                    mma_f16(acc[mt][nt], afl[mt], bfh[nt]);
        }

        if ((s & 7) == 7) {
            const int nc = s >> 3;
            #pragma unroll
            for (int mt = 0; mt < 2; mt++) {
                const int r0 = b0 + warp_m * 32 + mt * 16 + (lid >> 2);
                #pragma unroll
                for (int nt = 0; nt < 4; nt++) {
                    const int h = nc * 128 + warp_n * 32 + nt * 8 + (lid & 3) * 2;
                    const float bx = biasS[h], by = biasS[h+1];
                    float t0 = tanhf(acc[mt][nt][0] + bx);
                    float t1 = tanhf(acc[mt][nt][1] + by);
                    float t2 = tanhf(acc[mt][nt][2] + bx);
                    float t3 = tanhf(acc[mt][nt][3] + by);
                    if (z == 0) {
                        *(float2*)&g_h2[(size_t)r0 * HN + h]       = make_float2(t0, t1);
                        *(float2*)&g_h2[(size_t)(r0 + 8) * HN + h] = make_float2(t2, t3);
                        *(__half2*)&g_d2h[(size_t)r0 * HN + h] =
                            __floats2half2_rn(1.f - t0*t0, 1.f - t1*t1);
                        *(__half2*)&g_d2h[(size_t)(r0 + 8) * HN + h] =
                            __floats2half2_rn(1.f - t2*t2, 1.f - t3*t3);
                    } else {
                        *(float2*)&g_g2[(size_t)r0 * HN + h]       = make_float2(t0, t1);
                        *(float2*)&g_g2[(size_t)(r0 + 8) * HN + h] = make_float2(t2, t3);
                    }
                    acc[mt][nt][0] = 0.f; acc[mt][nt][1] = 0.f;
                    acc[mt][nt][2] = 0.f; acc[mt][nt][3] = 0.f;
                }
            }
        }

        if (s < 31) {
            uint4* dh = (uint4*)((__half*)(smem + C2_B + ((s+1) & 1) * B_BUF)
                                 + pb_row * B_STRIDE + pb_col);
            uint4* dl = (uint4*)((__half*)(smem + C2_B + 2*B_BUF + ((s+1) & 1) * B_BUF)
                                 + pb_row * B_STRIDE + pb_col);
            #pragma unroll
            for (int j = 0; j < 4; j++) { dh[j] = preh[j]; dl[j] = prel[j]; }
            __syncthreads();
        }
    }
}

// ---------------------------------------------------------------------------
// K3 (tiled GEMM, fp32, 64-row tiles -> 128 CTAs) — verified round 13
// ---------------------------------------------------------------------------
#define K3_TK 16
__global__ __launch_bounds__(256, 2) void k3_kernel(
    const float* __restrict__ W3, const float* __restrict__ b3,
    const float* __restrict__ V3, const float* __restrict__ c3,
    float* __restrict__ out)
{
    __shared__ float As[K3_TK][68];
    __shared__ float Bs[K3_TK][68];
    const int z = blockIdx.y;
    const float* __restrict__ in   = z ? g_g2 : g_h2;
    const float* __restrict__ W    = z ? V3 : W3;
    const float* __restrict__ bias = z ? c3 : b3;

    const int b0 = blockIdx.x * 64;
    const int t  = threadIdx.x;
    const int tx = t & 15, ty = t >> 4;
    const int lrow = t >> 2;
    const int lk4  = (t & 3) * 4;

    float acc[4][4];
    #pragma unroll
    for (int i = 0; i < 4; i++)
        #pragma unroll
        for (int j = 0; j < 4; j++) acc[i][j] = 0.f;

    float4 apre, bpre;
    apre = *(const float4*)&in[(b0 + lrow) * HN + lk4];
    bpre = *(const float4*)&W [lrow * HN + lk4];

    for (int kt = 0; kt < HN / K3_TK; kt++) {
        __syncthreads();
        As[lk4+0][lrow] = apre.x;
        As[lk4+1][lrow] = apre.y;
        As[lk4+2][lrow] = apre.z;
        As[lk4+3][lrow] = apre.w;
        Bs[lk4+0][lrow] = bpre.x;
        Bs[lk4+1][lrow] = bpre.y;
        Bs[lk4+2][lrow] = bpre.z;
        Bs[lk4+3][lrow] = bpre.w;
        __syncthreads();
        if (kt + 1 < HN / K3_TK) {
            int k0n = (kt + 1) * K3_TK;
            apre = *(const float4*)&in[(b0 + lrow) * HN + k0n + lk4];
            bpre = *(const float4*)&W [lrow * HN + k0n + lk4];
        }
        #pragma unroll
        for (int kk = 0; kk < K3_TK; kk++) {
            float a[4], bq[4];
            *(float4*)&a[0]  = *(const float4*)&As[kk][ty*4];
            *(float4*)&bq[0] = *(const float4*)&Bs[kk][tx*4];
            #pragma unroll
            for (int i = 0; i < 4; i++)
                #pragma unroll
                for (int j = 0; j < 4; j++)
                    acc[i][j] = fmaf(a[i], bq[j], acc[i][j]);
        }
    }

    #pragma unroll
    for (int j = 0; j < 4; j++) {
        const int dd = tx*4 + j;
        const float bb = bias[dd];
        #pragma unroll
        for (int i = 0; i < 4; i++) {
            const int b = b0 + ty*4 + i;
            float x = acc[i][j] + bb;
            if (z == 0) {
                out[b * (2*DN) + dd] = x;
            } else {
                g_q[b * DN + dd] = (x > 20.f) ? x : log1pf(expf(x));
            }
        }
    }
}

// ---------------------------------------------------------------------------
// K4 (single-pass fp16 mma.sync, 128-wide k-chunks): per CTA (one d, 128 b)
//   16 steps (4 n-chunks x 4 k-chunks of 128), double-buffered 32KB B chunks,
//   coalesced W1 column via g_w1t.
// ---------------------------------------------------------------------------
#define B4_STRIDE 136                           /* halves; 272B row stride */
#define B4_BUF    (128*B4_STRIDE*2)             /* 34816 B per buffer */
#define SM_JP    0
#define SM_W1C   0
#define SM_W3R   2048
#define SM_A     4096
#define SM_B     (SM_A + 128*A_STRIDE*2)        /* 137216 */
#define SM_TOT   (SM_B + 2*B4_BUF)              /* 206848 */

__global__ __launch_bounds__(256) void k4_kernel(
    const float* __restrict__ states,
    const float* __restrict__ W3,
    float* __restrict__ out)
{
    extern __shared__ char smem[];
    const uint32_t sb = smem_u32(smem);
    float* W1c = (float*)(smem + SM_W1C);
    float* W3r = (float*)(smem + SM_W3R);

    const int t   = threadIdx.x;
    const int lid = t & 31;
    const int wid = t >> 5;
    const int warp_m = wid >> 1;       // 0..3 -> 32 rows each
    const int warp_n = wid & 1;        // 0..1 -> 64 h each
    const int d  = blockIdx.y;
    const int b0 = blockIdx.x * 128;

    // coalesced: W1 column from pre-transposed g_w1t, W3 row contiguous
    for (int k = t; k < HN; k += 256) {
        W1c[k] = g_w1t[d * HN + k];
        W3r[k] = W3[d * HN + k];
    }
    __syncthreads();

    // ---- build A = fp16(d1*W1col): 2 threads per row, 256 k each ----
    {
        const int row   = t >> 1;
        const int kbase = (t & 1) * 256;
        const __half* d1p = &g_d1h[(size_t)(b0 + row) * HN + kbase];
        __half* arow = (__half*)(smem + SM_A) + row * A_STRIDE + kbase;
        #pragma unroll 8
        for (int kk = 0; kk < 256; kk += 8) {
            __half2 rp[4];
            *(uint4*)rp = *(const uint4*)&d1p[kk];
            __half2 ob[4];
            #pragma unroll
            for (int j = 0; j < 4; j++) {
                float2 v = __half22float2(rp[j]);
                ob[j] = __floats2half2_rn(v.x * W1c[kbase + kk + 2*j],
                                          v.y * W1c[kbase + kk + 2*j + 1]);
            }
            *(uint4*)&arow[kk] = *(uint4*)ob;
        }
    }

    const int lgrp = lid >> 3;
    const int lr   = lid & 7;
    const uint32_t a_row  = warp_m * 32 + (lgrp & 1) * 8 + lr;
    const uint32_t a_koff = (lgrp >> 1) * 8;
    const uint32_t b_nrow = warp_n * 64 + (lgrp >> 1) * 8 + lr;
    const uint32_t b_koff = (lgrp & 1) * 8;

    float acc[2][8][4];
    #pragma unroll
    for (int mt = 0; mt < 2; mt++)
        #pragma unroll
        for (int nt = 0; nt < 8; nt++)
            #pragma unroll
            for (int j = 0; j < 4; j++) acc[mt][nt][j] = 0.f;

    float Jp[2][2] = {{0.f, 0.f}, {0.f, 0.f}};

    // B prefetch: each thread covers 64 halves (128B) of a 128x128 chunk
    const int pb_row = t >> 1;
    const int pb_col = (t & 1) * 64;
    uint4 pre[8];
    {
        const uint4* src = (const uint4*)&g_w2h[(size_t)pb_row * HN + pb_col];
        #pragma unroll
        for (int j = 0; j < 8; j++) pre[j] = src[j];
    }
    {
        uint4* dst = (uint4*)((__half*)(smem + SM_B) + pb_row * B4_STRIDE + pb_col);
        #pragma unroll
        for (int j = 0; j < 8; j++) dst[j] = pre[j];
    }
    __syncthreads();

    for (int s = 0; s < 16; s++) {
        // prefetch next 128x128 B chunk
        if (s < 15) {
            const int sn = s + 1;
            const size_t off = (size_t)((sn >> 2) * 128 + pb_row) * HN + (sn & 3) * 128 + pb_col;
            const uint4* src = (const uint4*)&g_w2h[off];
            #pragma unroll
            for (int j = 0; j < 8; j++) pre[j] = src[j];
        }

        const uint32_t bbase = sb + SM_B + (uint32_t)(s & 1) * B4_BUF;
        const int kt = s & 3;
        #pragma unroll
        for (int ks = 0; ks < 8; ks++) {
            const int kabs = kt * 128 + ks * 16;
            uint32_t af[2][4], bf[8][2];
            #pragma unroll
            for (int mt = 0; mt < 2; mt++)
                ldsm4(af[mt], sb + SM_A + ((a_row + mt*16) * A_STRIDE + kabs + a_koff) * 2);
            #pragma unroll
            for (int pr = 0; pr < 4; pr++) {
                uint32_t r[4];
                ldsm4(r, bbase + ((b_nrow + pr*16) * B4_STRIDE + ks*16 + b_koff) * 2);
                bf[2*pr][0] = r[0]; bf[2*pr][1] = r[1];
                bf[2*pr+1][0] = r[2]; bf[2*pr+1][1] = r[3];
            }
            #pragma unroll
            for (int mt = 0; mt < 2; mt++)
                #pragma unroll
                for (int nt = 0; nt < 8; nt++)
                    mma_f16(acc[mt][nt], af[mt], bf[nt]);
        }

        // drain S tile into J partials at the end of each 128-h n-chunk
        if ((s & 3) == 3) {
            const int nc = s >> 2;
            #pragma unroll
            for (int mt = 0; mt < 2; mt++) {
                const int bA = b0 + warp_m * 32 + mt * 16 + (lid >> 2);
                const __half* d2a = &g_d2h[(size_t)bA * HN];
                const __half* d2c = &g_d2h[(size_t)(bA + 8) * HN];
                #pragma unroll
                for (int nt = 0; nt < 8; nt++) {
                    const int h = nc * 128 + warp_n * 64 + nt * 8 + (lid & 3) * 2;
                    const float w3x = W3r[h], w3y = W3r[h+1];
                    float2 va = __half22float2(*(const __half2*)&d2a[h]);
                    float2 vc = __half22float2(*(const __half2*)&d2c[h]);
                    Jp[mt][0] = fmaf(acc[mt][nt][0] * va.x, w3x,
                                fmaf(acc[mt][nt][1] * va.y, w3y, Jp[mt][0]));
                    Jp[mt][1] = fmaf(acc[mt][nt][2] * vc.x, w3x,
                                fmaf(acc[mt][nt][3] * vc.y, w3y, Jp[mt][1]));
                    acc[mt][nt][0] = 0.f; acc[mt][nt][1] = 0.f;
                    acc[mt][nt][2] = 0.f; acc[mt][nt][3] = 0.f;
                }
            }
        }

        if (s < 15) {
            uint4* dst = (uint4*)((__half*)(smem + SM_B + ((s+1) & 1) * B4_BUF)
                                  + pb_row * B4_STRIDE + pb_col);
            #pragma unroll
            for (int j = 0; j < 8; j++) dst[j] = pre[j];
            __syncthreads();
        }
    }

    #pragma unroll
    for (int mt = 0; mt < 2; mt++)
        #pragma unroll
        for (int hh = 0; hh < 2; hh++) {
            float v = Jp[mt][hh];
            v += __shfl_xor_sync(0xffffffffu, v, 1);
            v += __shfl_xor_sync(0xffffffffu, v, 2);
            Jp[mt][hh] = v;
        }

    float* Jpart = (float*)(smem + SM_JP);
    __syncthreads();
    if ((lid & 3) == 0) {
        #pragma unroll
        for (int mt = 0; mt < 2; mt++)
            #pragma unroll
            for (int hh = 0; hh < 2; hh++) {
                const int row = warp_m * 32 + mt * 16 + hh * 8 + (lid >> 2);
                Jpart[warp_n * 128 + row] = Jp[mt][hh];
            }
    }
    __syncthreads();
    if (t < 128) {
        const float J = Jpart[t] + Jpart[128 + t];
        const int b = b0 + t;
        const float sigma = states[(size_t)b * (2*DN) + DN + d];
        const float q     = g_q[(size_t)b * DN + d];
        out[(size_t)b * (2*DN) + DN + d] = 2.f * J * sigma + q;
    }
}

// ---------------------------------------------------------------------------
extern "C" void kernel_launch(void* const* d_in, const int* in_sizes, int n_in,
                              void* d_out, int out_size) {
    const float* states = (const float*)d_in[1];
    const float* W1 = (const float*)d_in[2];
    const float* b1 = (const float*)d_in[3];
    const float* W2 = (const float*)d_in[4];
    const float* b2 = (const float*)d_in[5];
    const float* W3 = (const float*)d_in[6];
    const float* b3 = (const float*)d_in[7];
    const float* V1 = (const float*)d_in[8];
    const float* c1 = (const float*)d_in[9];
    const float* V2 = (const float*)d_in[10];
    const float* c2 = (const float*)d_in[11];
    const float* V3 = (const float*)d_in[12];
    const float* c3 = (const float*)d_in[13];
    float* out = (float*)d_out;

    cudaFuncSetAttribute(k2_kernel, cudaFuncAttributeMaxDynamicSharedMemorySize, C2_TOT);
    cudaFuncSetAttribute(k4_kernel, cudaFuncAttributeMaxDynamicSharedMemorySize, SM_TOT);

    k0_kernel<<<512, 512>>>(W2, V2);
    k0b_kernel<<<DN, 512>>>(W1);
    k1_kernel<<<BN/8, 512>>>(states, W1, b1, V1, c1);
    k2_kernel<<<dim3(BN/64, 2), 256, C2_TOT>>>(b2, c2);
    k3_kernel<<<dim3(BN/64, 2), 256>>>(W3, b3, V3, c3, out);
    k4_kernel<<<dim3(BN/128, DN), 256, SM_TOT>>>(states, W3, out);
}

// round 17
// speedup vs baseline: 1.2930x; 1.2930x over previous
#include <cuda_runtime.h>
#include <cuda_fp16.h>
#include <math.h>
#include <stdint.h>

#define BN 4096
#define DN 64
#define HN 512

// ---------------- scratch (__device__ globals; no allocation) ----------------
__device__ __half g_h1h[BN*HN];
__device__ __half g_h1l[BN*HN];
__device__ __half g_g1h[BN*HN];
__device__ __half g_g1l[BN*HN];
__device__ __half g_d1h[BN*HN];
__device__ __half g_d2h[BN*HN];
__device__ float  g_h2[BN*HN];
__device__ float  g_g2[BN*HN];
__device__ float  g_q [BN*DN];
__device__ float  g_w1t[DN*HN];     /* W1 transposed: [d][k] */
__device__ __half g_w2h[HN*HN];
__device__ __half g_w2l[HN*HN];
__device__ __half g_v2h[HN*HN];
__device__ __half g_v2l[HN*HN];

__device__ __forceinline__ uint32_t smem_u32(const void* p) {
    return (uint32_t)__cvta_generic_to_shared(p);
}

__device__ __forceinline__ void ldsm4(uint32_t* r, uint32_t addr) {
    asm volatile("ldmatrix.sync.aligned.m8n8.x4.shared.b16 {%0,%1,%2,%3}, [%4];"
        : "=r"(r[0]), "=r"(r[1]), "=r"(r[2]), "=r"(r[3]) : "r"(addr));
}

__device__ __forceinline__ void mma_f16(float* c, const uint32_t* a, const uint32_t* b) {
    asm volatile(
        "mma.sync.aligned.m16n8k16.row.col.f32.f16.f16.f32 "
        "{%0,%1,%2,%3}, {%4,%5,%6,%7}, {%8,%9}, {%0,%1,%2,%3};"
        : "+f"(c[0]), "+f"(c[1]), "+f"(c[2]), "+f"(c[3])
        : "r"(a[0]), "r"(a[1]), "r"(a[2]), "r"(a[3]), "r"(b[0]), "r"(b[1]));
}

// ---------------------------------------------------------------------------
// K0: W2, V2 -> fp16 hi/lo ;  K0b: W1 -> transposed fp32
// ---------------------------------------------------------------------------
__global__ void k0_kernel(const float* __restrict__ W2, const float* __restrict__ V2) {
    int i = blockIdx.x * 512 + threadIdx.x;
    float w = W2[i];
    __half wh = __float2half_rn(w);
    g_w2h[i] = wh;
    g_w2l[i] = __float2half_rn(w - __half2float(wh));
    float v = V2[i];
    __half vh = __float2half_rn(v);
    g_v2h[i] = vh;
    g_v2l[i] = __float2half_rn(v - __half2float(vh));
}

__global__ void k0b_kernel(const float* __restrict__ W1) {
    const int d = blockIdx.x;
    for (int k = threadIdx.x; k < HN; k += 512)
        g_w1t[d * HN + k] = W1[k * DN + d];
}

// ---------------------------------------------------------------------------
// K1: h1 = tanh(mu@W1^T + b1) -> fp16 hi/lo + d1h; g1 = tanh(mu@V1^T+c1) -> hi/lo
// ---------------------------------------------------------------------------
__global__ __launch_bounds__(512) void k1_kernel(
    const float* __restrict__ states,
    const float* __restrict__ W1, const float* __restrict__ b1,
    const float* __restrict__ V1, const float* __restrict__ c1)
{
    __shared__ float mu_s[8][64];
    const int b0 = blockIdx.x * 8;
    const int t = threadIdx.x;
    {
        int bb = t >> 6, dd = t & 63;
        mu_s[bb][dd] = states[(b0 + bb) * (2*DN) + dd];
    }
    __syncthreads();
    const int h = t;
    float acc1[8], acc2[8];
    #pragma unroll
    for (int i = 0; i < 8; i++) { acc1[i] = 0.f; acc2[i] = 0.f; }
    const float4* w1r = (const float4*)(W1 + h * DN);
    const float4* v1r = (const float4*)(V1 + h * DN);
    #pragma unroll
    for (int q = 0; q < DN/4; q++) {
        float4 w = w1r[q];
        float4 v = v1r[q];
        #pragma unroll
        for (int bb = 0; bb < 8; bb++) {
            float4 m = *(const float4*)&mu_s[bb][q*4];
            acc1[bb] += w.x*m.x + w.y*m.y + w.z*m.z + w.w*m.w;
            acc2[bb] += v.x*m.x + v.y*m.y + v.z*m.z + v.w*m.w;
        }
    }
    const float bw = b1[h], bv = c1[h];
    #pragma unroll
    for (int bb = 0; bb < 8; bb++) {
        int idx = (b0 + bb) * HN + h;
        float th = tanhf(acc1[bb] + bw);
        __half hh = __float2half_rn(th);
        g_h1h[idx] = hh;
        g_h1l[idx] = __float2half_rn(th - __half2float(hh));
        g_d1h[idx] = __float2half_rn(1.f - th*th);
        float tg = tanhf(acc2[bb] + bv);
        __half gh = __float2half_rn(tg);
        g_g1h[idx] = gh;
        g_g1l[idx] = __float2half_rn(tg - __half2float(gh));
    }
}

// ---------------------------------------------------------------------------
// K2 (split-fp16 tensor GEMM), verified round 11
// ---------------------------------------------------------------------------
#define A_STRIDE 520
#define B_STRIDE 72
#define B_BUF    (128*B_STRIDE*2)
#define C2_BIAS  0
#define C2_AH    4096
#define C2_AL    (C2_AH + 64*A_STRIDE*2)        /* 70656  */
#define C2_B     (C2_AL + 64*A_STRIDE*2)        /* 137216 */
#define C2_TOT   (C2_B + 4*B_BUF)               /* 210944 */

__global__ __launch_bounds__(256) void k2_kernel(
    const float* __restrict__ b2, const float* __restrict__ c2)
{
    extern __shared__ char smem[];
    const uint32_t sb = smem_u32(smem);
    float* biasS = (float*)(smem + C2_BIAS);

    const int t   = threadIdx.x;
    const int lid = t & 31;
    const int wid = t >> 5;
    const int warp_m = wid >> 2;
    const int warp_n = wid & 3;
    const int z  = blockIdx.y;
    const int b0 = blockIdx.x * 64;

    const __half* in_h = z ? g_g1h : g_h1h;
    const __half* in_l = z ? g_g1l : g_h1l;
    const __half* Bh   = z ? g_v2h : g_w2h;
    const __half* Bl   = z ? g_v2l : g_w2l;
    const float*  bias = z ? c2 : b2;

    for (int i = t; i < HN; i += 256) biasS[i] = bias[i];

    {
        const int row = t >> 2;
        const int kb  = (t & 3) * 128;
        const uint4* sh = (const uint4*)&in_h[(size_t)(b0 + row) * HN + kb];
        const uint4* sl = (const uint4*)&in_l[(size_t)(b0 + row) * HN + kb];
        uint4* dh = (uint4*)((__half*)(smem + C2_AH) + row * A_STRIDE + kb);
        uint4* dl = (uint4*)((__half*)(smem + C2_AL) + row * A_STRIDE + kb);
        #pragma unroll
        for (int j = 0; j < 16; j++) { dh[j] = sh[j]; dl[j] = sl[j]; }
    }

    const int lgrp = lid >> 3;
    const int lr   = lid & 7;
    const uint32_t a_row  = warp_m * 32 + (lgrp & 1) * 8 + lr;
    const uint32_t a_koff = (lgrp >> 1) * 8;
    const uint32_t b_nrow = warp_n * 32 + (lgrp >> 1) * 8 + lr;
    const uint32_t b_koff = (lgrp & 1) * 8;

    float acc[2][4][4];
    #pragma unroll
    for (int mt = 0; mt < 2; mt++)
        #pragma unroll
        for (int nt = 0; nt < 4; nt++)
            #pragma unroll
            for (int j = 0; j < 4; j++) acc[mt][nt][j] = 0.f;

    const int pb_row = t >> 1;
    const int pb_col = (t & 1) * 32;
    uint4 preh[4], prel[4];
    {
        const uint4* sh = (const uint4*)&Bh[(size_t)pb_row * HN + pb_col];
        const uint4* sl = (const uint4*)&Bl[(size_t)pb_row * HN + pb_col];
        #pragma unroll
        for (int j = 0; j < 4; j++) { preh[j] = sh[j]; prel[j] = sl[j]; }
    }
    {
        uint4* dh = (uint4*)((__half*)(smem + C2_B) + pb_row * B_STRIDE + pb_col);
        uint4* dl = (uint4*)((__half*)(smem + C2_B + 2*B_BUF) + pb_row * B_STRIDE + pb_col);
        #pragma unroll
        for (int j = 0; j < 4; j++) { dh[j] = preh[j]; dl[j] = prel[j]; }
    }
    __syncthreads();

    for (int s = 0; s < 32; s++) {
        if (s < 31) {
            const int sn = s + 1;
            const size_t off = (size_t)((sn >> 3) * 128 + pb_row) * HN + (sn & 7) * 64 + pb_col;
            const uint4* sh = (const uint4*)&Bh[off];
            const uint4* sl = (const uint4*)&Bl[off];
            #pragma unroll
            for (int j = 0; j < 4; j++) { preh[j] = sh[j]; prel[j] = sl[j]; }
        }

        const uint32_t bh_base = sb + C2_B + (uint32_t)(s & 1) * B_BUF;
        const uint32_t bl_base = bh_base + 2*B_BUF;
        const int kt = s & 7;
        #pragma unroll
        for (int ks = 0; ks < 4; ks++) {
            const int kabs = kt * 64 + ks * 16;
            uint32_t afh[2][4], afl[2][4], bfh[4][2], bfl[4][2];
            #pragma unroll
            for (int mt = 0; mt < 2; mt++) {
                ldsm4(afh[mt], sb + C2_AH + ((a_row + mt*16) * A_STRIDE + kabs + a_koff) * 2);
                ldsm4(afl[mt], sb + C2_AL + ((a_row + mt*16) * A_STRIDE + kabs + a_koff) * 2);
            }
            #pragma unroll
            for (int pr = 0; pr < 2; pr++) {
                uint32_t r[4];
                ldsm4(r, bh_base + ((b_nrow + pr*16) * B_STRIDE + ks*16 + b_koff) * 2);
                bfh[2*pr][0] = r[0]; bfh[2*pr][1] = r[1];
                bfh[2*pr+1][0] = r[2]; bfh[2*pr+1][1] = r[3];
                ldsm4(r, bl_base + ((b_nrow + pr*16) * B_STRIDE + ks*16 + b_koff) * 2);
                bfl[2*pr][0] = r[0]; bfl[2*pr][1] = r[1];
                bfl[2*pr+1][0] = r[2]; bfl[2*pr+1][1] = r[3];
            }
            #pragma unroll
            for (int mt = 0; mt < 2; mt++)
                #pragma unroll
                for (int nt = 0; nt < 4; nt++)
                    mma_f16(acc[mt][nt], afh[mt], bfh[nt]);
            #pragma unroll
            for (int mt = 0; mt < 2; mt++)
                #pragma unroll
                for (int nt = 0; nt < 4; nt++)
                    mma_f16(acc[mt][nt], afh[mt], bfl[nt]);
            #pragma unroll
            for (int mt = 0; mt < 2; mt++)
                #pragma unroll
                for (int nt = 0; nt < 4; nt++)
                    mma_f16(acc[mt][nt], afl[mt], bfh[nt]);
        }

        if ((s & 7) == 7) {
            const int nc = s >> 3;
            #pragma unroll
            for (int mt = 0; mt < 2; mt++) {
                const int r0 = b0 + warp_m * 32 + mt * 16 + (lid >> 2);
                #pragma unroll
                for (int nt = 0; nt < 4; nt++) {
                    const int h = nc * 128 + warp_n * 32 + nt * 8 + (lid & 3) * 2;
                    const float bx = biasS[h], by = biasS[h+1];
                    float t0 = tanhf(acc[mt][nt][0] + bx);
                    float t1 = tanhf(acc[mt][nt][1] + by);
                    float t2 = tanhf(acc[mt][nt][2] + bx);
                    float t3 = tanhf(acc[mt][nt][3] + by);
                    if (z == 0) {
                        *(float2*)&g_h2[(size_t)r0 * HN + h]       = make_float2(t0, t1);
                        *(float2*)&g_h2[(size_t)(r0 + 8) * HN + h] = make_float2(t2, t3);
                        *(__half2*)&g_d2h[(size_t)r0 * HN + h] =
                            __floats2half2_rn(1.f - t0*t0, 1.f - t1*t1);
                        *(__half2*)&g_d2h[(size_t)(r0 + 8) * HN + h] =
                            __floats2half2_rn(1.f - t2*t2, 1.f - t3*t3);
                    } else {
                        *(float2*)&g_g2[(size_t)r0 * HN + h]       = make_float2(t0, t1);
                        *(float2*)&g_g2[(size_t)(r0 + 8) * HN + h] = make_float2(t2, t3);
                    }
                    acc[mt][nt][0] = 0.f; acc[mt][nt][1] = 0.f;
                    acc[mt][nt][2] = 0.f; acc[mt][nt][3] = 0.f;
                }
            }
        }

        if (s < 31) {
            uint4* dh = (uint4*)((__half*)(smem + C2_B + ((s+1) & 1) * B_BUF)
                                 + pb_row * B_STRIDE + pb_col);
            uint4* dl = (uint4*)((__half*)(smem + C2_B + 2*B_BUF + ((s+1) & 1) * B_BUF)
                                 + pb_row * B_STRIDE + pb_col);
            #pragma unroll
            for (int j = 0; j < 4; j++) { dh[j] = preh[j]; dl[j] = prel[j]; }
            __syncthreads();
        }
    }
}

// ---------------------------------------------------------------------------
// K3 (tiled GEMM, fp32, 64-row tiles -> 128 CTAs) — verified round 13
// ---------------------------------------------------------------------------
#define K3_TK 16
__global__ __launch_bounds__(256, 2) void k3_kernel(
    const float* __restrict__ W3, const float* __restrict__ b3,
    const float* __restrict__ V3, const float* __restrict__ c3,
    float* __restrict__ out)
{
    __shared__ float As[K3_TK][68];
    __shared__ float Bs[K3_TK][68];
    const int z = blockIdx.y;
    const float* __restrict__ in   = z ? g_g2 : g_h2;
    const float* __restrict__ W    = z ? V3 : W3;
    const float* __restrict__ bias = z ? c3 : b3;

    const int b0 = blockIdx.x * 64;
    const int t  = threadIdx.x;
    const int tx = t & 15, ty = t >> 4;
    const int lrow = t >> 2;
    const int lk4  = (t & 3) * 4;

    float acc[4][4];
    #pragma unroll
    for (int i = 0; i < 4; i++)
        #pragma unroll
        for (int j = 0; j < 4; j++) acc[i][j] = 0.f;

    float4 apre, bpre;
    apre = *(const float4*)&in[(b0 + lrow) * HN + lk4];
    bpre = *(const float4*)&W [lrow * HN + lk4];

    for (int kt = 0; kt < HN / K3_TK; kt++) {
        __syncthreads();
        As[lk4+0][lrow] = apre.x;
        As[lk4+1][lrow] = apre.y;
        As[lk4+2][lrow] = apre.z;
        As[lk4+3][lrow] = apre.w;
        Bs[lk4+0][lrow] = bpre.x;
        Bs[lk4+1][lrow] = bpre.y;
        Bs[lk4+2][lrow] = bpre.z;
        Bs[lk4+3][lrow] = bpre.w;
        __syncthreads();
        if (kt + 1 < HN / K3_TK) {
            int k0n = (kt + 1) * K3_TK;
            apre = *(const float4*)&in[(b0 + lrow) * HN + k0n + lk4];
            bpre = *(const float4*)&W [lrow * HN + k0n + lk4];
        }
        #pragma unroll
        for (int kk = 0; kk < K3_TK; kk++) {
            float a[4], bq[4];
            *(float4*)&a[0]  = *(const float4*)&As[kk][ty*4];
            *(float4*)&bq[0] = *(const float4*)&Bs[kk][tx*4];
            #pragma unroll
            for (int i = 0; i < 4; i++)
                #pragma unroll
                for (int j = 0; j < 4; j++)
                    acc[i][j] = fmaf(a[i], bq[j], acc[i][j]);
        }
    }

    #pragma unroll
    for (int j = 0; j < 4; j++) {
        const int dd = tx*4 + j;
        const float bb = bias[dd];
        #pragma unroll
        for (int i = 0; i < 4; i++) {
            const int b = b0 + ty*4 + i;
            float x = acc[i][j] + bb;
            if (z == 0) {
                out[b * (2*DN) + dd] = x;
            } else {
                g_q[b * DN + dd] = (x > 20.f) ? x : log1pf(expf(x));
            }
        }
    }
}

// ---------------------------------------------------------------------------
// K4 (single-pass fp16 mma.sync): round-15 structure (64-wide k-chunks),
// only change: W1 column loaded coalesced from g_w1t.
// ---------------------------------------------------------------------------
#define SM_JP    0
#define SM_W1C   0
#define SM_W3R   2048
#define SM_A     4096
#define SM_B     (SM_A + 128*A_STRIDE*2)       /* 137216 */
#define SM_TOT   (SM_B + 2*B_BUF)              /* 174080 */

__global__ __launch_bounds__(256) void k4_kernel(
    const float* __restrict__ states,
    const float* __restrict__ W3,
    float* __restrict__ out)
{
    extern __shared__ char smem[];
    const uint32_t sb = smem_u32(smem);
    float* W1c = (float*)(smem + SM_W1C);
    float* W3r = (float*)(smem + SM_W3R);

    const int t   = threadIdx.x;
    const int lid = t & 31;
    const int wid = t >> 5;
    const int warp_m = wid >> 1;
    const int warp_n = wid & 1;
    const int d  = blockIdx.y;
    const int b0 = blockIdx.x * 128;

    for (int k = t; k < HN; k += 256) {
        W1c[k] = g_w1t[d * HN + k];
        W3r[k] = W3[d * HN + k];
    }
    __syncthreads();

    {
        const int row   = t >> 1;
        const int kbase = (t & 1) * 256;
        const __half* d1p = &g_d1h[(size_t)(b0 + row) * HN + kbase];
        __half* arow = (__half*)(smem + SM_A) + row * A_STRIDE + kbase;
        #pragma unroll 8
        for (int kk = 0; kk < 256; kk += 8) {
            __half2 rp[4];
            *(uint4*)rp = *(const uint4*)&d1p[kk];
            __half2 ob[4];
            #pragma unroll
            for (int j = 0; j < 4; j++) {
                float2 v = __half22float2(rp[j]);
                ob[j] = __floats2half2_rn(v.x * W1c[kbase + kk + 2*j],
                                          v.y * W1c[kbase + kk + 2*j + 1]);
            }
            *(uint4*)&arow[kk] = *(uint4*)ob;
        }
    }

    const int lgrp = lid >> 3;
    const int lr   = lid & 7;
    const uint32_t a_row  = warp_m * 32 + (lgrp & 1) * 8 + lr;
    const uint32_t a_koff = (lgrp >> 1) * 8;
    const uint32_t b_nrow = warp_n * 64 + (lgrp >> 1) * 8 + lr;
    const uint32_t b_koff = (lgrp & 1) * 8;

    float acc[2][8][4];
    #pragma unroll
    for (int mt = 0; mt < 2; mt++)
        #pragma unroll
        for (int nt = 0; nt < 8; nt++)
            #pragma unroll
            for (int j = 0; j < 4; j++) acc[mt][nt][j] = 0.f;

    float Jp[2][2] = {{0.f, 0.f}, {0.f, 0.f}};

    const int pb_row = t >> 1;
    const int pb_col = (t & 1) * 32;
    uint4 pre[4];
    {
        const uint4* src = (const uint4*)&g_w2h[(size_t)pb_row * HN + pb_col];
        #pragma unroll
        for (int j = 0; j < 4; j++) pre[j] = src[j];
    }
    {
        uint4* dst = (uint4*)((__half*)(smem + SM_B) + pb_row * B_STRIDE + pb_col);
        #pragma unroll
        for (int j = 0; j < 4; j++) dst[j] = pre[j];
    }
    __syncthreads();

    for (int s = 0; s < 32; s++) {
        if (s < 31) {
            const int sn = s + 1;
            const size_t off = (size_t)((sn >> 3) * 128 + pb_row) * HN + (sn & 7) * 64 + pb_col;
            const uint4* src = (const uint4*)&g_w2h[off];
            #pragma unroll
            for (int j = 0; j < 4; j++) pre[j] = src[j];
        }

        const uint32_t bbase = sb + SM_B + (uint32_t)(s & 1) * B_BUF;
        const int kt = s & 7;
        #pragma unroll
        for (int ks = 0; ks < 4; ks++) {
            const int kabs = kt * 64 + ks * 16;
            uint32_t af[2][4], bf[8][2];
            #pragma unroll
            for (int mt = 0; mt < 2; mt++)
                ldsm4(af[mt], sb + SM_A + ((a_row + mt*16) * A_STRIDE + kabs + a_koff) * 2);
            #pragma unroll
            for (int pr = 0; pr < 4; pr++) {
                uint32_t r[4];
                ldsm4(r, bbase + ((b_nrow + pr*16) * B_STRIDE + ks*16 + b_koff) * 2);
                bf[2*pr][0] = r[0]; bf[2*pr][1] = r[1];
                bf[2*pr+1][0] = r[2]; bf[2*pr+1][1] = r[3];
            }
            #pragma unroll
            for (int mt = 0; mt < 2; mt++)
                #pragma unroll
                for (int nt = 0; nt < 8; nt++)
                    mma_f16(acc[mt][nt], af[mt], bf[nt]);
        }

        if ((s & 7) == 7) {
            const int nc = s >> 3;
            #pragma unroll
            for (int mt = 0; mt < 2; mt++) {
                const int bA = b0 + warp_m * 32 + mt * 16 + (lid >> 2);
                const __half* d2a = &g_d2h[(size_t)bA * HN];
                const __half* d2c = &g_d2h[(size_t)(bA + 8) * HN];
                #pragma unroll
                for (int nt = 0; nt < 8; nt++) {
                    const int h = nc * 128 + warp_n * 64 + nt * 8 + (lid & 3) * 2;
                    const float w3x = W3r[h], w3y = W3r[h+1];
                    float2 va = __half22float2(*(const __half2*)&d2a[h]);
                    float2 vc = __half22float2(*(const __half2*)&d2c[h]);
                    Jp[mt][0] = fmaf(acc[mt][nt][0] * va.x, w3x,
                                fmaf(acc[mt][nt][1] * va.y, w3y, Jp[mt][0]));
                    Jp[mt][1] = fmaf(acc[mt][nt][2] * vc.x, w3x,
                                fmaf(acc[mt][nt][3] * vc.y, w3y, Jp[mt][1]));
                    acc[mt][nt][0] = 0.f; acc[mt][nt][1] = 0.f;
                    acc[mt][nt][2] = 0.f; acc[mt][nt][3] = 0.f;
                }
            }
        }

        if (s < 31) {
            uint4* dst = (uint4*)((__half*)(smem + SM_B + ((s+1) & 1) * B_BUF)
                                  + pb_row * B_STRIDE + pb_col);
            #pragma unroll
            for (int j = 0; j < 4; j++) dst[j] = pre[j];
            __syncthreads();
        }
    }

    #pragma unroll
    for (int mt = 0; mt < 2; mt++)
        #pragma unroll
        for (int hh = 0; hh < 2; hh++) {
            float v = Jp[mt][hh];
            v += __shfl_xor_sync(0xffffffffu, v, 1);
            v += __shfl_xor_sync(0xffffffffu, v, 2);
            Jp[mt][hh] = v;
        }

    float* Jpart = (float*)(smem + SM_JP);
    __syncthreads();
    if ((lid & 3) == 0) {
        #pragma unroll
        for (int mt = 0; mt < 2; mt++)
            #pragma unroll
            for (int hh = 0; hh < 2; hh++) {
                const int row = warp_m * 32 + mt * 16 + hh * 8 + (lid >> 2);
                Jpart[warp_n * 128 + row] = Jp[mt][hh];
            }
    }
    __syncthreads();
    if (t < 128) {
        const float J = Jpart[t] + Jpart[128 + t];
        const int b = b0 + t;
        const float sigma = states[(size_t)b * (2*DN) + DN + d];
        const float q     = g_q[(size_t)b * DN + d];
        out[(size_t)b * (2*DN) + DN + d] = 2.f * J * sigma + q;
    }
}

// ---------------------------------------------------------------------------
extern "C" void kernel_launch(void* const* d_in, const int* in_sizes, int n_in,
                              void* d_out, int out_size) {
    const float* states = (const float*)d_in[1];
    const float* W1 = (const float*)d_in[2];
    const float* b1 = (const float*)d_in[3];
    const float* W2 = (const float*)d_in[4];
    const float* b2 = (const float*)d_in[5];
    const float* W3 = (const float*)d_in[6];
    const float* b3 = (const float*)d_in[7];
    const float* V1 = (const float*)d_in[8];
    const float* c1 = (const float*)d_in[9];
    const float* V2 = (const float*)d_in[10];
    const float* c2 = (const float*)d_in[11];
    const float* V3 = (const float*)d_in[12];
    const float* c3 = (const float*)d_in[13];
    float* out = (float*)d_out;

    cudaFuncSetAttribute(k2_kernel, cudaFuncAttributeMaxDynamicSharedMemorySize, C2_TOT);
    cudaFuncSetAttribute(k4_kernel, cudaFuncAttributeMaxDynamicSharedMemorySize, SM_TOT);

    k0_kernel<<<512, 512>>>(W2, V2);
    k0b_kernel<<<DN, 512>>>(W1);
    k1_kernel<<<BN/8, 512>>>(states, W1, b1, V1, c1);
    k2_kernel<<<dim3(BN/64, 2), 256, C2_TOT>>>(b2, c2);
    k3_kernel<<<dim3(BN/64, 2), 256>>>(W3, b3, V3, c3, out);
    k4_kernel<<<dim3(BN/128, DN), 256, SM_TOT>>>(states, W3, out);
}